// round 6
// baseline (speedup 1.0000x reference)
#include <cuda_runtime.h>
#include <math.h>
#include <stdint.h>

// ---------------- constants ----------------
#define BATCH   32
#define CIN     3
#define IMGSZ   224
#define PATCH   16
#define GRIDSZ  14
#define NPATCH  196
#define DIM     768
#define NHEAD   12
#define NLAYER  12
#define DFF     3072
#define DHEAD   64
#define NCLS    100
#define KEEPN   137
#define LFULL   197   // 1 + 196
#define LKEPT   138   // 1 + 137

// ---------------- device scratch (no allocation allowed) ----------------
__device__ float g_patches[BATCH * NPATCH * DIM];
__device__ float g_embed  [BATCH * NPATCH * DIM];
__device__ float g_x      [BATCH * LFULL  * DIM];
__device__ float g_x2     [BATCH * LKEPT  * DIM];
__device__ float g_h      [BATCH * LFULL  * DIM];
__device__ float g_qkv    [BATCH * LFULL  * 3 * DIM];
__device__ float g_o      [BATCH * LFULL  * DIM];
__device__ float g_mlp    [BATCH * LFULL  * DFF];

// ---------------- helpers ----------------
__device__ __forceinline__ float gelu_tanh(float v) {
    float v3 = v * v * v;
    float t  = tanhf(0.7978845608028654f * (v + 0.044715f * v3));
    return 0.5f * v * (1.0f + t);
}

// ---------------- im2col: [B,C,224,224] -> [B*196, 768] ----------------
__global__ void im2col_k(const float* __restrict__ in, float* __restrict__ out) {
    int i = blockIdx.x * blockDim.x + threadIdx.x;
    if (i >= BATCH * NPATCH * DIM) return;
    int d = i % DIM;
    int p = (i / DIM) % NPATCH;
    int b = i / (DIM * NPATCH);
    int c  = d >> 8;
    int py = (d >> 4) & 15;
    int px = d & 15;
    int gy = p / GRIDSZ, gx = p % GRIDSZ;
    out[i] = in[((b * CIN + c) * IMGSZ + gy * PATCH + py) * IMGSZ + gx * PATCH + px];
}

// ---------------- assemble x = [cls|embed] + pos ----------------
__global__ void assemble_k(const float* __restrict__ embed, const float* __restrict__ cls,
                           const float* __restrict__ pos, float* __restrict__ x) {
    int i = blockIdx.x * blockDim.x + threadIdx.x;
    if (i >= BATCH * LFULL * DIM) return;
    int d = i % DIM;
    int r = (i / DIM) % LFULL;
    int b = i / (DIM * LFULL);
    float v = (r == 0) ? cls[d] : embed[((size_t)b * NPATCH + (r - 1)) * DIM + d];
    x[i] = v + pos[r * DIM + d];
}

// ---------------- GEMM with Kahan-compensated fp32 accumulation ----------------
// C[M,N] = A[M,K] @ W[K,N] + bias (+resid)(+gelu)
// flags: bit0 = gelu epilogue, bit1 = residual add (R[m*N+n])
__global__ __launch_bounds__(256) void gemm_k(
    const float* __restrict__ A, const float* __restrict__ W,
    const float* __restrict__ bias, const float* __restrict__ R,
    float* __restrict__ C, int M, int N, int K, int flags)
{
    __shared__ float As[16][64];
    __shared__ float Ws[16][64];

    int tid = threadIdx.x;
    int tx = tid & 15, ty = tid >> 4;
    int row0 = blockIdx.y << 6;
    int col0 = blockIdx.x << 6;

    int ar = tid >> 2;
    int ak = (tid & 3) << 2;
    int wk = tid >> 4;
    int wn = (tid & 15) << 2;

    bool arow_ok = (row0 + ar) < M;

    float acc[4][4], cmp[4][4];
#pragma unroll
    for (int i = 0; i < 4; i++)
#pragma unroll
        for (int j = 0; j < 4; j++) { acc[i][j] = 0.f; cmp[i][j] = 0.f; }

    for (int k0 = 0; k0 < K; k0 += 16) {
        float4 av = make_float4(0.f, 0.f, 0.f, 0.f);
        if (arow_ok)
            av = *(const float4*)(A + (size_t)(row0 + ar) * K + k0 + ak);
        As[ak + 0][ar] = av.x;
        As[ak + 1][ar] = av.y;
        As[ak + 2][ar] = av.z;
        As[ak + 3][ar] = av.w;

        int wcol = col0 + wn;
        const float* wp = W + (size_t)(k0 + wk) * N + wcol;
        if (wcol + 3 < N) {
            float4 wv = *(const float4*)wp;
            Ws[wk][wn + 0] = wv.x;
            Ws[wk][wn + 1] = wv.y;
            Ws[wk][wn + 2] = wv.z;
            Ws[wk][wn + 3] = wv.w;
        } else {
#pragma unroll
            for (int i = 0; i < 4; i++)
                Ws[wk][wn + i] = (wcol + i < N) ? wp[i] : 0.f;
        }
        __syncthreads();

#pragma unroll
        for (int kk = 0; kk < 16; kk++) {
            float a4[4], w4[4];
            *(float4*)a4 = *(const float4*)&As[kk][ty << 2];
            *(float4*)w4 = *(const float4*)&Ws[kk][tx << 2];
#pragma unroll
            for (int i = 0; i < 4; i++)
#pragma unroll
                for (int j = 0; j < 4; j++) {
                    // Kahan-FMA: y = a*w - c (exact product via FFMA), then compensated add
                    float y = fmaf(a4[i], w4[j], -cmp[i][j]);
                    float t = acc[i][j] + y;
                    cmp[i][j] = (t - acc[i][j]) - y;
                    acc[i][j] = t;
                }
        }
        __syncthreads();
    }

#pragma unroll
    for (int i = 0; i < 4; i++) {
        int m = row0 + (ty << 2) + i;
        if (m >= M) continue;
#pragma unroll
        for (int j = 0; j < 4; j++) {
            int n = col0 + (tx << 2) + j;
            if (n >= N) continue;
            float v = acc[i][j] + bias[n];
            if (flags & 2) v += R[(size_t)m * N + n];
            if (flags & 1) v = gelu_tanh(v);
            C[(size_t)m * N + n] = v;
        }
    }
}

// ---------------- LayerNorm: fp64 reductions ----------------
__global__ __launch_bounds__(256) void ln_k(const float* __restrict__ x,
                                            const float* __restrict__ gg,
                                            const float* __restrict__ bb,
                                            float* __restrict__ out) {
    int row = blockIdx.x;
    int t = threadIdx.x;
    const float* xr = x + (size_t)row * DIM;
    float v0 = xr[t], v1 = xr[t + 256], v2 = xr[t + 512];

    __shared__ double red[8];
    double s = (double)v0 + (double)v1 + (double)v2;
#pragma unroll
    for (int o = 16; o > 0; o >>= 1) s += __shfl_xor_sync(0xffffffffu, s, o);
    if ((t & 31) == 0) red[t >> 5] = s;
    __syncthreads();
    double tot = 0.0;
#pragma unroll
    for (int w = 0; w < 8; w++) tot += red[w];
    float mean = (float)(tot * (1.0 / 768.0));
    __syncthreads();

    float d0 = v0 - mean, d1 = v1 - mean, d2 = v2 - mean;
    double sq = (double)d0 * d0 + (double)d1 * d1 + (double)d2 * d2;
#pragma unroll
    for (int o = 16; o > 0; o >>= 1) sq += __shfl_xor_sync(0xffffffffu, sq, o);
    if ((t & 31) == 0) red[t >> 5] = sq;
    __syncthreads();
    double vtot = 0.0;
#pragma unroll
    for (int w = 0; w < 8; w++) vtot += red[w];
    float var = (float)(vtot * (1.0 / 768.0));
    float rstd = rsqrtf(var + 1e-6f);

    float* orow = out + (size_t)row * DIM;
    orow[t]       = d0 * rstd * gg[t]       + bb[t];
    orow[t + 256] = d1 * rstd * gg[t + 256] + bb[t + 256];
    orow[t + 512] = d2 * rstd * gg[t + 512] + bb[t + 512];
}

// ---------------- attention: two-pass softmax with exact max, accurate expf ----
__global__ __launch_bounds__(224) void attn_k(const float* __restrict__ qkv,
                                              float* __restrict__ o, int L) {
    int b = blockIdx.x / NHEAD;
    int h = blockIdx.x % NHEAD;
    __shared__ float Ks[64][DHEAD];
    __shared__ float Vs[64][DHEAD];
    int t = threadIdx.x;

    const float* base = qkv + (size_t)b * L * (3 * DIM);

    float qv[DHEAD];
    if (t < L) {
        const float* qp = base + (size_t)t * (3 * DIM) + h * DHEAD;
#pragma unroll
        for (int d = 0; d < DHEAD; d++) qv[d] = qp[d];
    }

    // ---- pass 1: exact row max of scores ----
    float mmax = -3.0e38f;
    for (int j0 = 0; j0 < L; j0 += 64) {
        int jn = min(64, L - j0);
        for (int e = t; e < jn * 16; e += blockDim.x) {
            int jj = e >> 4, q = e & 15;
            const float* kp = base + (size_t)(j0 + jj) * (3 * DIM) + DIM + h * DHEAD;
            *(float4*)&Ks[jj][q << 2] = *(const float4*)(kp + (q << 2));
        }
        __syncthreads();
        if (t < L) {
            for (int jj = 0; jj < jn; jj++) {
                float s = 0.f;
#pragma unroll
                for (int d = 0; d < DHEAD; d++) s = fmaf(qv[d], Ks[jj][d], s);
                mmax = fmaxf(mmax, s * 0.125f);
            }
        }
        __syncthreads();
    }

    // ---- pass 2: p = expf(s - max); sum and p@v, fixed max (no rescaling) ----
    float acc[DHEAD];
    float lsum = 0.f, lcmp = 0.f;
    if (t < L) {
#pragma unroll
        for (int d = 0; d < DHEAD; d++) acc[d] = 0.f;
    }
    for (int j0 = 0; j0 < L; j0 += 64) {
        int jn = min(64, L - j0);
        for (int e = t; e < jn * 32; e += blockDim.x) {
            int jj = e >> 5, q = e & 31;
            const float* kp = base + (size_t)(j0 + jj) * (3 * DIM) + DIM + h * DHEAD;
            if (q < 16)
                *(float4*)&Ks[jj][q << 2] = *(const float4*)(kp + (q << 2));
            else
                *(float4*)&Vs[jj][(q - 16) << 2] = *(const float4*)(kp + DIM + ((q - 16) << 2));
        }
        __syncthreads();
        if (t < L) {
            for (int jj = 0; jj < jn; jj++) {
                float s = 0.f;
#pragma unroll
                for (int d = 0; d < DHEAD; d++) s = fmaf(qv[d], Ks[jj][d], s);
                float p = expf(s * 0.125f - mmax);
                // Kahan on the softmax denominator
                float y = p - lcmp;
                float ts = lsum + y;
                lcmp = (ts - lsum) - y;
                lsum = ts;
#pragma unroll
                for (int d = 0; d < DHEAD; d++) acc[d] = fmaf(p, Vs[jj][d], acc[d]);
            }
        }
        __syncthreads();
    }

    if (t < L) {
        float inv = 1.0f / lsum;
        float* op = o + ((size_t)(b * L + t)) * DIM + h * DHEAD;
#pragma unroll
        for (int d = 0; d < DHEAD; d++) op[d] = acc[d] * inv;
    }
}

// ---------------- token selection after layer 3 (fp64 sims) ----------------
__global__ __launch_bounds__(256) void select_k(const float* __restrict__ x,
                                                float* __restrict__ x2) {
    int b = blockIdx.x;
    int t = threadIdx.x;
    __shared__ float cls_s[DIM];
    __shared__ float sim[NPATCH];
    __shared__ int   order[KEEPN];

    for (int d = t; d < DIM; d += 256) cls_s[d] = x[(size_t)(b * LFULL) * DIM + d];
    __syncthreads();

    if (t < NPATCH) {
        const float* row = x + (size_t)(b * LFULL + 1 + t) * DIM;
        double dot = 0.0, n2 = 0.0, c2 = 0.0;
        for (int d = 0; d < DIM; d++) {
            double xv = (double)row[d], cv = (double)cls_s[d];
            dot += cv * xv; n2 += xv * xv; c2 += cv * cv;
        }
        double den = sqrt(c2) * sqrt(n2);
        sim[t] = (float)(dot / fmax(den, 1e-8));
    }
    __syncthreads();

    if (t < NPATCH) {
        float sv = sim[t];
        int r = 0;
        for (int q = 0; q < NPATCH; q++) {
            float o = sim[q];
            r += (o > sv) || (o == sv && q < t);
        }
        if (r < KEEPN) order[r] = t;   // exact top_k order (descending, stable)
    }
    __syncthreads();

    for (int e = t; e < LKEPT * DIM; e += 256) {
        int r = e / DIM, d = e % DIM;
        int src = (r == 0) ? 0 : 1 + order[r - 1];
        x2[(size_t)(b * LKEPT + r) * DIM + d] = x[(size_t)(b * LFULL + src) * DIM + d];
    }
}

// ---------------- host driver ----------------
static void launch_gemm(const float* A, const float* W, const float* bias,
                        const float* R, float* C, int M, int N, int K, int flags) {
    dim3 grid((N + 63) / 64, (M + 63) / 64);
    gemm_k<<<grid, 256>>>(A, W, bias, R, C, M, N, K, flags);
}

extern "C" void kernel_launch(void* const* d_in, const int* in_sizes, int n_in,
                              void* d_out, int out_size) {
    const float* inputs    = (const float*)d_in[0];
    const float* patch_w   = (const float*)d_in[1];
    const float* patch_b   = (const float*)d_in[2];
    const float* cls_token = (const float*)d_in[3];
    const float* pos_embed = (const float*)d_in[4];
    const float* qkv_w     = (const float*)d_in[5];
    const float* qkv_b     = (const float*)d_in[6];
    const float* proj_w    = (const float*)d_in[7];
    const float* proj_b    = (const float*)d_in[8];
    const float* ln1_g     = (const float*)d_in[9];
    const float* ln1_b     = (const float*)d_in[10];
    const float* ln2_g     = (const float*)d_in[11];
    const float* ln2_b     = (const float*)d_in[12];
    const float* mlp_w1    = (const float*)d_in[13];
    const float* mlp_b1    = (const float*)d_in[14];
    const float* mlp_w2    = (const float*)d_in[15];
    const float* mlp_b2    = (const float*)d_in[16];
    const float* norm_g    = (const float*)d_in[17];
    const float* norm_b    = (const float*)d_in[18];
    const float* head_w    = (const float*)d_in[19];
    const float* head_b    = (const float*)d_in[20];

    float *p_pat, *p_emb, *p_x, *p_x2, *p_h, *p_qkv, *p_o, *p_mlp;
    cudaGetSymbolAddress((void**)&p_pat, g_patches);
    cudaGetSymbolAddress((void**)&p_emb, g_embed);
    cudaGetSymbolAddress((void**)&p_x,   g_x);
    cudaGetSymbolAddress((void**)&p_x2,  g_x2);
    cudaGetSymbolAddress((void**)&p_h,   g_h);
    cudaGetSymbolAddress((void**)&p_qkv, g_qkv);
    cudaGetSymbolAddress((void**)&p_o,   g_o);
    cudaGetSymbolAddress((void**)&p_mlp, g_mlp);

    // patch embed
    {
        int n = BATCH * NPATCH * DIM;
        im2col_k<<<(n + 255) / 256, 256>>>(inputs, p_pat);
        launch_gemm(p_pat, patch_w, patch_b, nullptr, p_emb, BATCH * NPATCH, DIM, DIM, 0);
        int n2 = BATCH * LFULL * DIM;
        assemble_k<<<(n2 + 255) / 256, 256>>>(p_emb, cls_token, pos_embed, p_x);
    }

    float* x = p_x;
    int L = LFULL;
    for (int n = 0; n < NLAYER; n++) {
        int M = BATCH * L;
        ln_k<<<M, 256>>>(x, ln1_g + n * DIM, ln1_b + n * DIM, p_h);
        launch_gemm(p_h, qkv_w + (size_t)n * DIM * 3 * DIM, qkv_b + n * 3 * DIM,
                    nullptr, p_qkv, M, 3 * DIM, DIM, 0);
        attn_k<<<BATCH * NHEAD, (L == LFULL) ? 224 : 160>>>(p_qkv, p_o, L);
        launch_gemm(p_o, proj_w + (size_t)n * DIM * DIM, proj_b + n * DIM,
                    x, x, M, DIM, DIM, 2);
        ln_k<<<M, 256>>>(x, ln2_g + n * DIM, ln2_b + n * DIM, p_h);
        launch_gemm(p_h, mlp_w1 + (size_t)n * DIM * DFF, mlp_b1 + n * DFF,
                    nullptr, p_mlp, M, DFF, DIM, 1);
        launch_gemm(p_mlp, mlp_w2 + (size_t)n * DFF * DIM, mlp_b2 + n * DIM,
                    x, x, M, DIM, DFF, 2);
        if (n == 3) {
            select_k<<<BATCH, 256>>>(x, p_x2);
            x = p_x2;
            L = LKEPT;
        }
    }

    ln_k<<<BATCH * LKEPT, 256>>>(x, norm_g, norm_b, p_h);
    launch_gemm(p_h, head_w, head_b, nullptr, (float*)d_out,
                BATCH * LKEPT, NCLS, DIM, 0);
}

// round 7
// speedup vs baseline: 1.4174x; 1.4174x over previous
#include <cuda_runtime.h>
#include <math.h>
#include <stdint.h>

// ---------------- constants ----------------
#define BATCH   32
#define CIN     3
#define IMGSZ   224
#define PATCH   16
#define GRIDSZ  14
#define NPATCH  196
#define DIM     768
#define NHEAD   12
#define NLAYER  12
#define DFF     3072
#define DHEAD   64
#define NCLS    100
#define KEEPN   137
#define LFULL   197   // 1 + 196
#define LKEPT   138   // 1 + 137

// ---------------- device scratch (no allocation allowed) ----------------
__device__ float g_patches[BATCH * NPATCH * DIM];
__device__ float g_embed  [BATCH * NPATCH * DIM];
__device__ float g_x      [BATCH * LFULL  * DIM];
__device__ float g_x2     [BATCH * LKEPT  * DIM];
__device__ float g_h      [BATCH * LFULL  * DIM];
__device__ float g_qkv    [BATCH * LFULL  * 3 * DIM];
__device__ float g_o      [BATCH * LFULL  * DIM];
__device__ float g_mlp    [BATCH * LFULL  * DFF];

// ---------------- helpers ----------------
__device__ __forceinline__ float gelu_tanh(float v) {
    float v3 = v * v * v;
    float t  = tanhf(0.7978845608028654f * (v + 0.044715f * v3));
    return 0.5f * v * (1.0f + t);
}

// ---------------- im2col: [B,C,224,224] -> [B*196, 768] ----------------
__global__ void im2col_k(const float* __restrict__ in, float* __restrict__ out) {
    int i = blockIdx.x * blockDim.x + threadIdx.x;
    if (i >= BATCH * NPATCH * DIM) return;
    int d = i % DIM;
    int p = (i / DIM) % NPATCH;
    int b = i / (DIM * NPATCH);
    int c  = d >> 8;
    int py = (d >> 4) & 15;
    int px = d & 15;
    int gy = p / GRIDSZ, gx = p % GRIDSZ;
    out[i] = in[((b * CIN + c) * IMGSZ + gy * PATCH + py) * IMGSZ + gx * PATCH + px];
}

// ---------------- assemble x = [cls|embed] + pos ----------------
__global__ void assemble_k(const float* __restrict__ embed, const float* __restrict__ cls,
                           const float* __restrict__ pos, float* __restrict__ x) {
    int i = blockIdx.x * blockDim.x + threadIdx.x;
    if (i >= BATCH * LFULL * DIM) return;
    int d = i % DIM;
    int r = (i / DIM) % LFULL;
    int b = i / (DIM * LFULL);
    float v = (r == 0) ? cls[d] : embed[((size_t)b * NPATCH + (r - 1)) * DIM + d];
    x[i] = v + pos[r * DIM + d];
}

// ---------------- GEMM (templated: Kahan-compensated or plain fp32) ----------------
// C[M,N] = A[M,K] @ W[K,N] + bias (+resid)(+gelu)
// flags: bit0 = gelu epilogue, bit1 = residual add (R[m*N+n])
template <bool KAHAN>
__global__ __launch_bounds__(256) void gemm_k(
    const float* __restrict__ A, const float* __restrict__ W,
    const float* __restrict__ bias, const float* __restrict__ R,
    float* __restrict__ C, int M, int N, int K, int flags)
{
    __shared__ float As[16][64];
    __shared__ float Ws[16][64];

    int tid = threadIdx.x;
    int tx = tid & 15, ty = tid >> 4;
    int row0 = blockIdx.y << 6;
    int col0 = blockIdx.x << 6;

    int ar = tid >> 2;
    int ak = (tid & 3) << 2;
    int wk = tid >> 4;
    int wn = (tid & 15) << 2;

    bool arow_ok = (row0 + ar) < M;

    float acc[4][4], cmp[4][4];
#pragma unroll
    for (int i = 0; i < 4; i++)
#pragma unroll
        for (int j = 0; j < 4; j++) { acc[i][j] = 0.f; cmp[i][j] = 0.f; }

    for (int k0 = 0; k0 < K; k0 += 16) {
        float4 av = make_float4(0.f, 0.f, 0.f, 0.f);
        if (arow_ok)
            av = *(const float4*)(A + (size_t)(row0 + ar) * K + k0 + ak);
        As[ak + 0][ar] = av.x;
        As[ak + 1][ar] = av.y;
        As[ak + 2][ar] = av.z;
        As[ak + 3][ar] = av.w;

        int wcol = col0 + wn;
        const float* wp = W + (size_t)(k0 + wk) * N + wcol;
        if (wcol + 3 < N) {
            float4 wv = *(const float4*)wp;
            Ws[wk][wn + 0] = wv.x;
            Ws[wk][wn + 1] = wv.y;
            Ws[wk][wn + 2] = wv.z;
            Ws[wk][wn + 3] = wv.w;
        } else {
#pragma unroll
            for (int i = 0; i < 4; i++)
                Ws[wk][wn + i] = (wcol + i < N) ? wp[i] : 0.f;
        }
        __syncthreads();

#pragma unroll
        for (int kk = 0; kk < 16; kk++) {
            float a4[4], w4[4];
            *(float4*)a4 = *(const float4*)&As[kk][ty << 2];
            *(float4*)w4 = *(const float4*)&Ws[kk][tx << 2];
#pragma unroll
            for (int i = 0; i < 4; i++)
#pragma unroll
                for (int j = 0; j < 4; j++) {
                    if (KAHAN) {
                        // Kahan-FMA: exact product via FFMA, then compensated add
                        float y = fmaf(a4[i], w4[j], -cmp[i][j]);
                        float t = acc[i][j] + y;
                        cmp[i][j] = (t - acc[i][j]) - y;
                        acc[i][j] = t;
                    } else {
                        acc[i][j] = fmaf(a4[i], w4[j], acc[i][j]);
                    }
                }
        }
        __syncthreads();
    }

#pragma unroll
    for (int i = 0; i < 4; i++) {
        int m = row0 + (ty << 2) + i;
        if (m >= M) continue;
#pragma unroll
        for (int j = 0; j < 4; j++) {
            int n = col0 + (tx << 2) + j;
            if (n >= N) continue;
            float v = acc[i][j] + bias[n];
            if (flags & 2) v += R[(size_t)m * N + n];
            if (flags & 1) v = gelu_tanh(v);
            C[(size_t)m * N + n] = v;
        }
    }
}

// ---------------- LayerNorm, fp64 reductions (pre-selection path) ----------------
__global__ __launch_bounds__(256) void ln_k(const float* __restrict__ x,
                                            const float* __restrict__ gg,
                                            const float* __restrict__ bb,
                                            float* __restrict__ out) {
    int row = blockIdx.x;
    int t = threadIdx.x;
    const float* xr = x + (size_t)row * DIM;
    float v0 = xr[t], v1 = xr[t + 256], v2 = xr[t + 512];

    __shared__ double red[8];
    double s = (double)v0 + (double)v1 + (double)v2;
#pragma unroll
    for (int o = 16; o > 0; o >>= 1) s += __shfl_xor_sync(0xffffffffu, s, o);
    if ((t & 31) == 0) red[t >> 5] = s;
    __syncthreads();
    double tot = 0.0;
#pragma unroll
    for (int w = 0; w < 8; w++) tot += red[w];
    float mean = (float)(tot * (1.0 / 768.0));
    __syncthreads();

    float d0 = v0 - mean, d1 = v1 - mean, d2 = v2 - mean;
    double sq = (double)d0 * d0 + (double)d1 * d1 + (double)d2 * d2;
#pragma unroll
    for (int o = 16; o > 0; o >>= 1) sq += __shfl_xor_sync(0xffffffffu, sq, o);
    if ((t & 31) == 0) red[t >> 5] = sq;
    __syncthreads();
    double vtot = 0.0;
#pragma unroll
    for (int w = 0; w < 8; w++) vtot += red[w];
    float var = (float)(vtot * (1.0 / 768.0));
    float rstd = rsqrtf(var + 1e-6f);

    float* orow = out + (size_t)row * DIM;
    orow[t]       = d0 * rstd * gg[t]       + bb[t];
    orow[t + 256] = d1 * rstd * gg[t + 256] + bb[t + 256];
    orow[t + 512] = d2 * rstd * gg[t + 512] + bb[t + 512];
}

// ---------------- LayerNorm, fp32 reductions (post-selection fast path) ----------
__global__ __launch_bounds__(256) void ln_fast_k(const float* __restrict__ x,
                                                 const float* __restrict__ gg,
                                                 const float* __restrict__ bb,
                                                 float* __restrict__ out) {
    int row = blockIdx.x;
    int t = threadIdx.x;
    const float* xr = x + (size_t)row * DIM;
    float v0 = xr[t], v1 = xr[t + 256], v2 = xr[t + 512];

    __shared__ float red[8];
    float s = v0 + v1 + v2;
#pragma unroll
    for (int o = 16; o > 0; o >>= 1) s += __shfl_xor_sync(0xffffffffu, s, o);
    if ((t & 31) == 0) red[t >> 5] = s;
    __syncthreads();
    float tot = 0.f;
#pragma unroll
    for (int w = 0; w < 8; w++) tot += red[w];
    float mean = tot * (1.0f / 768.0f);
    __syncthreads();

    float d0 = v0 - mean, d1 = v1 - mean, d2 = v2 - mean;
    float sq = d0 * d0 + d1 * d1 + d2 * d2;
#pragma unroll
    for (int o = 16; o > 0; o >>= 1) sq += __shfl_xor_sync(0xffffffffu, sq, o);
    if ((t & 31) == 0) red[t >> 5] = sq;
    __syncthreads();
    float vtot = 0.f;
#pragma unroll
    for (int w = 0; w < 8; w++) vtot += red[w];
    float var = vtot * (1.0f / 768.0f);
    float rstd = rsqrtf(var + 1e-6f);

    float* orow = out + (size_t)row * DIM;
    orow[t]       = d0 * rstd * gg[t]       + bb[t];
    orow[t + 256] = d1 * rstd * gg[t + 256] + bb[t + 256];
    orow[t + 512] = d2 * rstd * gg[t + 512] + bb[t + 512];
}

// ---------------- attention: two-pass softmax with exact max, accurate expf ----
__global__ __launch_bounds__(224) void attn_k(const float* __restrict__ qkv,
                                              float* __restrict__ o, int L) {
    int b = blockIdx.x / NHEAD;
    int h = blockIdx.x % NHEAD;
    __shared__ float Ks[64][DHEAD];
    __shared__ float Vs[64][DHEAD];
    int t = threadIdx.x;

    const float* base = qkv + (size_t)b * L * (3 * DIM);

    float qv[DHEAD];
    if (t < L) {
        const float* qp = base + (size_t)t * (3 * DIM) + h * DHEAD;
#pragma unroll
        for (int d = 0; d < DHEAD; d++) qv[d] = qp[d];
    }

    // ---- pass 1: exact row max of scores ----
    float mmax = -3.0e38f;
    for (int j0 = 0; j0 < L; j0 += 64) {
        int jn = min(64, L - j0);
        for (int e = t; e < jn * 16; e += blockDim.x) {
            int jj = e >> 4, q = e & 15;
            const float* kp = base + (size_t)(j0 + jj) * (3 * DIM) + DIM + h * DHEAD;
            *(float4*)&Ks[jj][q << 2] = *(const float4*)(kp + (q << 2));
        }
        __syncthreads();
        if (t < L) {
            for (int jj = 0; jj < jn; jj++) {
                float s = 0.f;
#pragma unroll
                for (int d = 0; d < DHEAD; d++) s = fmaf(qv[d], Ks[jj][d], s);
                mmax = fmaxf(mmax, s * 0.125f);
            }
        }
        __syncthreads();
    }

    // ---- pass 2: p = expf(s - max); sum and p@v, fixed max ----
    float acc[DHEAD];
    float lsum = 0.f, lcmp = 0.f;
    if (t < L) {
#pragma unroll
        for (int d = 0; d < DHEAD; d++) acc[d] = 0.f;
    }
    for (int j0 = 0; j0 < L; j0 += 64) {
        int jn = min(64, L - j0);
        for (int e = t; e < jn * 32; e += blockDim.x) {
            int jj = e >> 5, q = e & 31;
            const float* kp = base + (size_t)(j0 + jj) * (3 * DIM) + DIM + h * DHEAD;
            if (q < 16)
                *(float4*)&Ks[jj][q << 2] = *(const float4*)(kp + (q << 2));
            else
                *(float4*)&Vs[jj][(q - 16) << 2] = *(const float4*)(kp + DIM + ((q - 16) << 2));
        }
        __syncthreads();
        if (t < L) {
            for (int jj = 0; jj < jn; jj++) {
                float s = 0.f;
#pragma unroll
                for (int d = 0; d < DHEAD; d++) s = fmaf(qv[d], Ks[jj][d], s);
                float p = expf(s * 0.125f - mmax);
                float y = p - lcmp;
                float ts = lsum + y;
                lcmp = (ts - lsum) - y;
                lsum = ts;
#pragma unroll
                for (int d = 0; d < DHEAD; d++) acc[d] = fmaf(p, Vs[jj][d], acc[d]);
            }
        }
        __syncthreads();
    }

    if (t < L) {
        float inv = 1.0f / lsum;
        float* op = o + ((size_t)(b * L + t)) * DIM + h * DHEAD;
#pragma unroll
        for (int d = 0; d < DHEAD; d++) op[d] = acc[d] * inv;
    }
}

// ---------------- token selection after layer 3 (fp64 sims) ----------------
__global__ __launch_bounds__(256) void select_k(const float* __restrict__ x,
                                                float* __restrict__ x2) {
    int b = blockIdx.x;
    int t = threadIdx.x;
    __shared__ float cls_s[DIM];
    __shared__ float sim[NPATCH];
    __shared__ int   order[KEEPN];

    for (int d = t; d < DIM; d += 256) cls_s[d] = x[(size_t)(b * LFULL) * DIM + d];
    __syncthreads();

    if (t < NPATCH) {
        const float* row = x + (size_t)(b * LFULL + 1 + t) * DIM;
        double dot = 0.0, n2 = 0.0, c2 = 0.0;
        for (int d = 0; d < DIM; d++) {
            double xv = (double)row[d], cv = (double)cls_s[d];
            dot += cv * xv; n2 += xv * xv; c2 += cv * cv;
        }
        double den = sqrt(c2) * sqrt(n2);
        sim[t] = (float)(dot / fmax(den, 1e-8));
    }
    __syncthreads();

    if (t < NPATCH) {
        float sv = sim[t];
        int r = 0;
        for (int q = 0; q < NPATCH; q++) {
            float o = sim[q];
            r += (o > sv) || (o == sv && q < t);
        }
        if (r < KEEPN) order[r] = t;   // exact top_k order (descending, stable)
    }
    __syncthreads();

    for (int e = t; e < LKEPT * DIM; e += 256) {
        int r = e / DIM, d = e % DIM;
        int src = (r == 0) ? 0 : 1 + order[r - 1];
        x2[(size_t)(b * LKEPT + r) * DIM + d] = x[(size_t)(b * LFULL + src) * DIM + d];
    }
}

// ---------------- host driver ----------------
static void launch_gemm(const float* A, const float* W, const float* bias,
                        const float* R, float* C, int M, int N, int K, int flags,
                        bool kahan) {
    dim3 grid((N + 63) / 64, (M + 63) / 64);
    if (kahan)
        gemm_k<true><<<grid, 256>>>(A, W, bias, R, C, M, N, K, flags);
    else
        gemm_k<false><<<grid, 256>>>(A, W, bias, R, C, M, N, K, flags);
}

extern "C" void kernel_launch(void* const* d_in, const int* in_sizes, int n_in,
                              void* d_out, int out_size) {
    const float* inputs    = (const float*)d_in[0];
    const float* patch_w   = (const float*)d_in[1];
    const float* patch_b   = (const float*)d_in[2];
    const float* cls_token = (const float*)d_in[3];
    const float* pos_embed = (const float*)d_in[4];
    const float* qkv_w     = (const float*)d_in[5];
    const float* qkv_b     = (const float*)d_in[6];
    const float* proj_w    = (const float*)d_in[7];
    const float* proj_b    = (const float*)d_in[8];
    const float* ln1_g     = (const float*)d_in[9];
    const float* ln1_b     = (const float*)d_in[10];
    const float* ln2_g     = (const float*)d_in[11];
    const float* ln2_b     = (const float*)d_in[12];
    const float* mlp_w1    = (const float*)d_in[13];
    const float* mlp_b1    = (const float*)d_in[14];
    const float* mlp_w2    = (const float*)d_in[15];
    const float* mlp_b2    = (const float*)d_in[16];
    const float* norm_g    = (const float*)d_in[17];
    const float* norm_b    = (const float*)d_in[18];
    const float* head_w    = (const float*)d_in[19];
    const float* head_b    = (const float*)d_in[20];

    float *p_pat, *p_emb, *p_x, *p_x2, *p_h, *p_qkv, *p_o, *p_mlp;
    cudaGetSymbolAddress((void**)&p_pat, g_patches);
    cudaGetSymbolAddress((void**)&p_emb, g_embed);
    cudaGetSymbolAddress((void**)&p_x,   g_x);
    cudaGetSymbolAddress((void**)&p_x2,  g_x2);
    cudaGetSymbolAddress((void**)&p_h,   g_h);
    cudaGetSymbolAddress((void**)&p_qkv, g_qkv);
    cudaGetSymbolAddress((void**)&p_o,   g_o);
    cudaGetSymbolAddress((void**)&p_mlp, g_mlp);

    // patch embed (pre-selection path: Kahan)
    {
        int n = BATCH * NPATCH * DIM;
        im2col_k<<<(n + 255) / 256, 256>>>(inputs, p_pat);
        launch_gemm(p_pat, patch_w, patch_b, nullptr, p_emb, BATCH * NPATCH, DIM, DIM, 0, true);
        int n2 = BATCH * LFULL * DIM;
        assemble_k<<<(n2 + 255) / 256, 256>>>(p_emb, cls_token, pos_embed, p_x);
    }

    float* x = p_x;
    int L = LFULL;
    for (int n = 0; n < NLAYER; n++) {
        int M = BATCH * L;
        bool pre = (n <= 3);   // numerics before/at selection must stay exact-track
        if (pre) ln_k     <<<M, 256>>>(x, ln1_g + n * DIM, ln1_b + n * DIM, p_h);
        else     ln_fast_k<<<M, 256>>>(x, ln1_g + n * DIM, ln1_b + n * DIM, p_h);
        launch_gemm(p_h, qkv_w + (size_t)n * DIM * 3 * DIM, qkv_b + n * 3 * DIM,
                    nullptr, p_qkv, M, 3 * DIM, DIM, 0, pre);
        attn_k<<<BATCH * NHEAD, (L == LFULL) ? 224 : 160>>>(p_qkv, p_o, L);
        launch_gemm(p_o, proj_w + (size_t)n * DIM * DIM, proj_b + n * DIM,
                    x, x, M, DIM, DIM, 2, pre);
        if (pre) ln_k     <<<M, 256>>>(x, ln2_g + n * DIM, ln2_b + n * DIM, p_h);
        else     ln_fast_k<<<M, 256>>>(x, ln2_g + n * DIM, ln2_b + n * DIM, p_h);
        launch_gemm(p_h, mlp_w1 + (size_t)n * DIM * DFF, mlp_b1 + n * DFF,
                    nullptr, p_mlp, M, DFF, DIM, 1, pre);
        launch_gemm(p_mlp, mlp_w2 + (size_t)n * DFF * DIM, mlp_b2 + n * DIM,
                    x, x, M, DIM, DFF, 2, pre);
        if (n == 3) {
            select_k<<<BATCH, 256>>>(x, p_x2);
            x = p_x2;
            L = LKEPT;
        }
    }

    ln_fast_k<<<BATCH * LKEPT, 256>>>(x, norm_g, norm_b, p_h);
    launch_gemm(p_h, head_w, head_b, nullptr, (float*)d_out,
                BATCH * LKEPT, NCLS, DIM, 0, false);
}

// round 11
// speedup vs baseline: 1.5564x; 1.0981x over previous
#include <cuda_runtime.h>
#include <math.h>
#include <stdint.h>

// ---------------- constants ----------------
#define BATCH   32
#define CIN     3
#define IMGSZ   224
#define PATCH   16
#define GRIDSZ  14
#define NPATCH  196
#define DIM     768
#define NHEAD   12
#define NLAYER  12
#define DFF     3072
#define DHEAD   64
#define NCLS    100
#define KEEPN   137
#define LFULL   197   // 1 + 196
#define LKEPT   138   // 1 + 137

// ---------------- device scratch (no allocation allowed) ----------------
__device__ float g_patches[BATCH * NPATCH * DIM];
__device__ float g_embed  [BATCH * NPATCH * DIM];
__device__ float g_x      [BATCH * LFULL  * DIM];
__device__ float g_x2     [BATCH * LKEPT  * DIM];
__device__ float g_h      [BATCH * LFULL  * DIM];
__device__ float g_qkv    [BATCH * LFULL  * 3 * DIM];
__device__ float g_o      [BATCH * LFULL  * DIM];
__device__ float g_mlp    [BATCH * LFULL  * DFF];

// ---------------- helpers ----------------
__device__ __forceinline__ float gelu_tanh(float v) {
    float v3 = v * v * v;
    float t  = tanhf(0.7978845608028654f * (v + 0.044715f * v3));
    return 0.5f * v * (1.0f + t);
}

// ---------------- im2col: [B,C,224,224] -> [B*196, 768] ----------------
__global__ void im2col_k(const float* __restrict__ in, float* __restrict__ out) {
    int i = blockIdx.x * blockDim.x + threadIdx.x;
    if (i >= BATCH * NPATCH * DIM) return;
    int d = i % DIM;
    int p = (i / DIM) % NPATCH;
    int b = i / (DIM * NPATCH);
    int c  = d >> 8;
    int py = (d >> 4) & 15;
    int px = d & 15;
    int gy = p / GRIDSZ, gx = p % GRIDSZ;
    out[i] = in[((b * CIN + c) * IMGSZ + gy * PATCH + py) * IMGSZ + gx * PATCH + px];
}

// ---------------- assemble x = [cls|embed] + pos ----------------
__global__ void assemble_k(const float* __restrict__ embed, const float* __restrict__ cls,
                           const float* __restrict__ pos, float* __restrict__ x) {
    int i = blockIdx.x * blockDim.x + threadIdx.x;
    if (i >= BATCH * LFULL * DIM) return;
    int d = i % DIM;
    int r = (i / DIM) % LFULL;
    int b = i / (DIM * LFULL);
    float v = (r == 0) ? cls[d] : embed[((size_t)b * NPATCH + (r - 1)) * DIM + d];
    x[i] = v + pos[r * DIM + d];
}

// ---------------- Kahan GEMM, 64x64 tile, guarded N (head only) ----------------
// flags: bit0 = gelu epilogue, bit1 = residual add
__global__ __launch_bounds__(256) void gemm_kahan_k(
    const float* __restrict__ A, const float* __restrict__ W,
    const float* __restrict__ bias, const float* __restrict__ R,
    float* __restrict__ C, int M, int N, int K, int flags)
{
    __shared__ float As[16][64];
    __shared__ float Ws[16][64];

    int tid = threadIdx.x;
    int tx = tid & 15, ty = tid >> 4;
    int row0 = blockIdx.y << 6;
    int col0 = blockIdx.x << 6;

    int ar = tid >> 2;
    int ak = (tid & 3) << 2;
    int wk = tid >> 4;
    int wn = (tid & 15) << 2;

    bool arow_ok = (row0 + ar) < M;

    float acc[4][4], cmp[4][4];
#pragma unroll
    for (int i = 0; i < 4; i++)
#pragma unroll
        for (int j = 0; j < 4; j++) { acc[i][j] = 0.f; cmp[i][j] = 0.f; }

    for (int k0 = 0; k0 < K; k0 += 16) {
        float4 av = make_float4(0.f, 0.f, 0.f, 0.f);
        if (arow_ok)
            av = *(const float4*)(A + (size_t)(row0 + ar) * K + k0 + ak);
        As[ak + 0][ar] = av.x;
        As[ak + 1][ar] = av.y;
        As[ak + 2][ar] = av.z;
        As[ak + 3][ar] = av.w;

        int wcol = col0 + wn;
        const float* wp = W + (size_t)(k0 + wk) * N + wcol;
        if (wcol + 3 < N) {
            float4 wv = *(const float4*)wp;
            Ws[wk][wn + 0] = wv.x;
            Ws[wk][wn + 1] = wv.y;
            Ws[wk][wn + 2] = wv.z;
            Ws[wk][wn + 3] = wv.w;
        } else {
#pragma unroll
            for (int i = 0; i < 4; i++)
                Ws[wk][wn + i] = (wcol + i < N) ? wp[i] : 0.f;
        }
        __syncthreads();

#pragma unroll
        for (int kk = 0; kk < 16; kk++) {
            float a4[4], w4[4];
            *(float4*)a4 = *(const float4*)&As[kk][ty << 2];
            *(float4*)w4 = *(const float4*)&Ws[kk][tx << 2];
#pragma unroll
            for (int i = 0; i < 4; i++)
#pragma unroll
                for (int j = 0; j < 4; j++) {
                    float y = fmaf(a4[i], w4[j], -cmp[i][j]);
                    float t = acc[i][j] + y;
                    cmp[i][j] = (t - acc[i][j]) - y;
                    acc[i][j] = t;
                }
        }
        __syncthreads();
    }

#pragma unroll
    for (int i = 0; i < 4; i++) {
        int m = row0 + (ty << 2) + i;
        if (m >= M) continue;
#pragma unroll
        for (int j = 0; j < 4; j++) {
            int n = col0 + (tx << 2) + j;
            if (n >= N) continue;
            float v = acc[i][j] + bias[n];
            if (flags & 2) v += R[(size_t)m * N + n];
            if (flags & 1) v = gelu_tanh(v);
            C[(size_t)m * N + n] = v;
        }
    }
}

// ---------------- GEMM, 128x64 tile, 8x4 microtile, templated accumulation -------
// Requires N % 64 == 0 and K % 16 == 0. KAHAN=true is bit-identical to the 64x64
// Kahan kernel (per-element accumulation order over k is unchanged).
template <bool KAHAN>
__global__ __launch_bounds__(256) void gemm128_t(
    const float* __restrict__ A, const float* __restrict__ W,
    const float* __restrict__ bias, const float* __restrict__ R,
    float* __restrict__ C, int M, int N, int K, int flags)
{
    __shared__ float As[16][128];
    __shared__ float Ws[16][64];

    int tid = threadIdx.x;
    int tx = tid & 15, ty = tid >> 4;
    int row0 = blockIdx.y << 7;
    int col0 = blockIdx.x << 6;

    int ar = tid >> 1;            // 0..127
    int ak = (tid & 1) << 3;      // 0 or 8
    int wk = tid >> 4;            // 0..15
    int wn = (tid & 15) << 2;     // 0..60

    bool arow_ok = (row0 + ar) < M;

    float acc[8][4], cmp[8][4];
#pragma unroll
    for (int i = 0; i < 8; i++)
#pragma unroll
        for (int j = 0; j < 4; j++) { acc[i][j] = 0.f; cmp[i][j] = 0.f; }

    for (int k0 = 0; k0 < K; k0 += 16) {
#pragma unroll
        for (int u = 0; u < 2; u++) {
            float4 av = make_float4(0.f, 0.f, 0.f, 0.f);
            if (arow_ok)
                av = *(const float4*)(A + (size_t)(row0 + ar) * K + k0 + ak + (u << 2));
            As[ak + (u << 2) + 0][ar] = av.x;
            As[ak + (u << 2) + 1][ar] = av.y;
            As[ak + (u << 2) + 2][ar] = av.z;
            As[ak + (u << 2) + 3][ar] = av.w;
        }
        {
            float4 wv = *(const float4*)(W + (size_t)(k0 + wk) * N + col0 + wn);
            Ws[wk][wn + 0] = wv.x;
            Ws[wk][wn + 1] = wv.y;
            Ws[wk][wn + 2] = wv.z;
            Ws[wk][wn + 3] = wv.w;
        }
        __syncthreads();

#pragma unroll
        for (int kk = 0; kk < 16; kk++) {
            float a8[8], w4[4];
            *(float4*)&a8[0] = *(const float4*)&As[kk][ty << 3];
            *(float4*)&a8[4] = *(const float4*)&As[kk][(ty << 3) + 4];
            *(float4*)w4 = *(const float4*)&Ws[kk][tx << 2];
#pragma unroll
            for (int i = 0; i < 8; i++)
#pragma unroll
                for (int j = 0; j < 4; j++) {
                    if (KAHAN) {
                        float y = fmaf(a8[i], w4[j], -cmp[i][j]);
                        float t = acc[i][j] + y;
                        cmp[i][j] = (t - acc[i][j]) - y;
                        acc[i][j] = t;
                    } else {
                        acc[i][j] = fmaf(a8[i], w4[j], acc[i][j]);
                    }
                }
        }
        __syncthreads();
    }

#pragma unroll
    for (int i = 0; i < 8; i++) {
        int m = row0 + (ty << 3) + i;
        if (m >= M) continue;
        int n0 = col0 + (tx << 2);
#pragma unroll
        for (int j = 0; j < 4; j++) {
            int n = n0 + j;
            float v = acc[i][j] + bias[n];
            if (flags & 2) v += R[(size_t)m * N + n];
            if (flags & 1) v = gelu_tanh(v);
            C[(size_t)m * N + n] = v;
        }
    }
}

// ---------------- LayerNorm, fp64 reductions (pre-selection path) ----------------
__global__ __launch_bounds__(256) void ln_k(const float* __restrict__ x,
                                            const float* __restrict__ gg,
                                            const float* __restrict__ bb,
                                            float* __restrict__ out) {
    int row = blockIdx.x;
    int t = threadIdx.x;
    const float* xr = x + (size_t)row * DIM;
    float v0 = xr[t], v1 = xr[t + 256], v2 = xr[t + 512];

    __shared__ double red[8];
    double s = (double)v0 + (double)v1 + (double)v2;
#pragma unroll
    for (int o = 16; o > 0; o >>= 1) s += __shfl_xor_sync(0xffffffffu, s, o);
    if ((t & 31) == 0) red[t >> 5] = s;
    __syncthreads();
    double tot = 0.0;
#pragma unroll
    for (int w = 0; w < 8; w++) tot += red[w];
    float mean = (float)(tot * (1.0 / 768.0));
    __syncthreads();

    float d0 = v0 - mean, d1 = v1 - mean, d2 = v2 - mean;
    double sq = (double)d0 * d0 + (double)d1 * d1 + (double)d2 * d2;
#pragma unroll
    for (int o = 16; o > 0; o >>= 1) sq += __shfl_xor_sync(0xffffffffu, sq, o);
    if ((t & 31) == 0) red[t >> 5] = sq;
    __syncthreads();
    double vtot = 0.0;
#pragma unroll
    for (int w = 0; w < 8; w++) vtot += red[w];
    float var = (float)(vtot * (1.0 / 768.0));
    float rstd = rsqrtf(var + 1e-6f);

    float* orow = out + (size_t)row * DIM;
    orow[t]       = d0 * rstd * gg[t]       + bb[t];
    orow[t + 256] = d1 * rstd * gg[t + 256] + bb[t + 256];
    orow[t + 512] = d2 * rstd * gg[t + 512] + bb[t + 512];
}

// ---------------- LayerNorm, fp32 reductions (post-selection fast path) ----------
__global__ __launch_bounds__(256) void ln_fast_k(const float* __restrict__ x,
                                                 const float* __restrict__ gg,
                                                 const float* __restrict__ bb,
                                                 float* __restrict__ out) {
    int row = blockIdx.x;
    int t = threadIdx.x;
    const float* xr = x + (size_t)row * DIM;
    float v0 = xr[t], v1 = xr[t + 256], v2 = xr[t + 512];

    __shared__ float red[8];
    float s = v0 + v1 + v2;
#pragma unroll
    for (int o = 16; o > 0; o >>= 1) s += __shfl_xor_sync(0xffffffffu, s, o);
    if ((t & 31) == 0) red[t >> 5] = s;
    __syncthreads();
    float tot = 0.f;
#pragma unroll
    for (int w = 0; w < 8; w++) tot += red[w];
    float mean = tot * (1.0f / 768.0f);
    __syncthreads();

    float d0 = v0 - mean, d1 = v1 - mean, d2 = v2 - mean;
    float sq = d0 * d0 + d1 * d1 + d2 * d2;
#pragma unroll
    for (int o = 16; o > 0; o >>= 1) sq += __shfl_xor_sync(0xffffffffu, sq, o);
    if ((t & 31) == 0) red[t >> 5] = sq;
    __syncthreads();
    float vtot = 0.f;
#pragma unroll
    for (int w = 0; w < 8; w++) vtot += red[w];
    float var = vtot * (1.0f / 768.0f);
    float rstd = rsqrtf(var + 1e-6f);

    float* orow = out + (size_t)row * DIM;
    orow[t]       = d0 * rstd * gg[t]       + bb[t];
    orow[t + 256] = d1 * rstd * gg[t + 256] + bb[t + 256];
    orow[t + 512] = d2 * rstd * gg[t + 512] + bb[t + 512];
}

// ---------------- attention, two-pass exact max (pre-selection path) -------------
__global__ __launch_bounds__(224) void attn_k(const float* __restrict__ qkv,
                                              float* __restrict__ o, int L) {
    int b = blockIdx.x / NHEAD;
    int h = blockIdx.x % NHEAD;
    __shared__ float Ks[64][DHEAD];
    __shared__ float Vs[64][DHEAD];
    int t = threadIdx.x;

    const float* base = qkv + (size_t)b * L * (3 * DIM);

    float qv[DHEAD];
    if (t < L) {
        const float* qp = base + (size_t)t * (3 * DIM) + h * DHEAD;
#pragma unroll
        for (int d = 0; d < DHEAD; d++) qv[d] = qp[d];
    }

    float mmax = -3.0e38f;
    for (int j0 = 0; j0 < L; j0 += 64) {
        int jn = min(64, L - j0);
        for (int e = t; e < jn * 16; e += blockDim.x) {
            int jj = e >> 4, q = e & 15;
            const float* kp = base + (size_t)(j0 + jj) * (3 * DIM) + DIM + h * DHEAD;
            *(float4*)&Ks[jj][q << 2] = *(const float4*)(kp + (q << 2));
        }
        __syncthreads();
        if (t < L) {
            for (int jj = 0; jj < jn; jj++) {
                float s = 0.f;
#pragma unroll
                for (int d = 0; d < DHEAD; d++) s = fmaf(qv[d], Ks[jj][d], s);
                mmax = fmaxf(mmax, s * 0.125f);
            }
        }
        __syncthreads();
    }

    float acc[DHEAD];
    float lsum = 0.f, lcmp = 0.f;
    if (t < L) {
#pragma unroll
        for (int d = 0; d < DHEAD; d++) acc[d] = 0.f;
    }
    for (int j0 = 0; j0 < L; j0 += 64) {
        int jn = min(64, L - j0);
        for (int e = t; e < jn * 32; e += blockDim.x) {
            int jj = e >> 5, q = e & 31;
            const float* kp = base + (size_t)(j0 + jj) * (3 * DIM) + DIM + h * DHEAD;
            if (q < 16)
                *(float4*)&Ks[jj][q << 2] = *(const float4*)(kp + (q << 2));
            else
                *(float4*)&Vs[jj][(q - 16) << 2] = *(const float4*)(kp + DIM + ((q - 16) << 2));
        }
        __syncthreads();
        if (t < L) {
            for (int jj = 0; jj < jn; jj++) {
                float s = 0.f;
#pragma unroll
                for (int d = 0; d < DHEAD; d++) s = fmaf(qv[d], Ks[jj][d], s);
                float p = expf(s * 0.125f - mmax);
                float y = p - lcmp;
                float ts = lsum + y;
                lcmp = (ts - lsum) - y;
                lsum = ts;
#pragma unroll
                for (int d = 0; d < DHEAD; d++) acc[d] = fmaf(p, Vs[jj][d], acc[d]);
            }
        }
        __syncthreads();
    }

    if (t < L) {
        float inv = 1.0f / lsum;
        float* op = o + ((size_t)(b * L + t)) * DIM + h * DHEAD;
#pragma unroll
        for (int d = 0; d < DHEAD; d++) op[d] = acc[d] * inv;
    }
}

// ---------------- attention, single-pass online softmax (post-selection) ---------
__global__ __launch_bounds__(160) void attn_fast_k(const float* __restrict__ qkv,
                                                   float* __restrict__ o, int L) {
    int b = blockIdx.x / NHEAD;
    int h = blockIdx.x % NHEAD;
    __shared__ float Ks[64][DHEAD];
    __shared__ float Vs[64][DHEAD];
    int t = threadIdx.x;

    const float* base = qkv + (size_t)b * L * (3 * DIM);

    float qv[DHEAD], acc[DHEAD];
    float mmax = -3.0e38f, lsum = 0.f;
    if (t < L) {
        const float* qp = base + (size_t)t * (3 * DIM) + h * DHEAD;
#pragma unroll
        for (int d = 0; d < DHEAD; d++) { qv[d] = qp[d]; acc[d] = 0.f; }
    }

    for (int j0 = 0; j0 < L; j0 += 64) {
        int jn = min(64, L - j0);
        for (int e = t; e < jn * 32; e += blockDim.x) {
            int jj = e >> 5, q = e & 31;
            const float* kp = base + (size_t)(j0 + jj) * (3 * DIM) + DIM + h * DHEAD;
            if (q < 16)
                *(float4*)&Ks[jj][q << 2] = *(const float4*)(kp + (q << 2));
            else
                *(float4*)&Vs[jj][(q - 16) << 2] = *(const float4*)(kp + DIM + ((q - 16) << 2));
        }
        __syncthreads();
        if (t < L) {
            for (int jj = 0; jj < jn; jj++) {
                float s = 0.f;
#pragma unroll
                for (int d = 0; d < DHEAD; d++) s = fmaf(qv[d], Ks[jj][d], s);
                s *= 0.125f;
                float nm   = fmaxf(mmax, s);
                float corr = __expf(mmax - nm);
                float p    = __expf(s - nm);
                lsum = lsum * corr + p;
#pragma unroll
                for (int d = 0; d < DHEAD; d++) acc[d] = fmaf(acc[d], corr, p * Vs[jj][d]);
                mmax = nm;
            }
        }
        __syncthreads();
    }

    if (t < L) {
        float inv = 1.0f / lsum;
        float* op = o + ((size_t)(b * L + t)) * DIM + h * DHEAD;
#pragma unroll
        for (int d = 0; d < DHEAD; d++) op[d] = acc[d] * inv;
    }
}

// ---------------- token selection after layer 3 (fp64 sims) ----------------
__global__ __launch_bounds__(256) void select_k(const float* __restrict__ x,
                                                float* __restrict__ x2) {
    int b = blockIdx.x;
    int t = threadIdx.x;
    __shared__ float cls_s[DIM];
    __shared__ float sim[NPATCH];
    __shared__ int   order[KEEPN];

    for (int d = t; d < DIM; d += 256) cls_s[d] = x[(size_t)(b * LFULL) * DIM + d];
    __syncthreads();

    if (t < NPATCH) {
        const float* row = x + (size_t)(b * LFULL + 1 + t) * DIM;
        double dot = 0.0, n2 = 0.0, c2 = 0.0;
        for (int d = 0; d < DIM; d++) {
            double xv = (double)row[d], cv = (double)cls_s[d];
            dot += cv * xv; n2 += xv * xv; c2 += cv * cv;
        }
        double den = sqrt(c2) * sqrt(n2);
        sim[t] = (float)(dot / fmax(den, 1e-8));
    }
    __syncthreads();

    if (t < NPATCH) {
        float sv = sim[t];
        int r = 0;
        for (int q = 0; q < NPATCH; q++) {
            float o = sim[q];
            r += (o > sv) || (o == sv && q < t);
        }
        if (r < KEEPN) order[r] = t;
    }
    __syncthreads();

    for (int e = t; e < LKEPT * DIM; e += 256) {
        int r = e / DIM, d = e % DIM;
        int src = (r == 0) ? 0 : 1 + order[r - 1];
        x2[(size_t)(b * LKEPT + r) * DIM + d] = x[(size_t)(b * LFULL + src) * DIM + d];
    }
}

// ---------------- host driver ----------------
static void launch_gemm(const float* A, const float* W, const float* bias,
                        const float* R, float* C, int M, int N, int K, int flags,
                        bool kahan) {
    if (N & 63) {
        dim3 grid((N + 63) / 64, (M + 63) / 64);
        gemm_kahan_k<<<grid, 256>>>(A, W, bias, R, C, M, N, K, flags);
    } else {
        dim3 grid(N / 64, (M + 127) / 128);
        if (kahan)
            gemm128_t<true><<<grid, 256>>>(A, W, bias, R, C, M, N, K, flags);
        else
            gemm128_t<false><<<grid, 256>>>(A, W, bias, R, C, M, N, K, flags);
    }
}

extern "C" void kernel_launch(void* const* d_in, const int* in_sizes, int n_in,
                              void* d_out, int out_size) {
    const float* inputs    = (const float*)d_in[0];
    const float* patch_w   = (const float*)d_in[1];
    const float* patch_b   = (const float*)d_in[2];
    const float* cls_token = (const float*)d_in[3];
    const float* pos_embed = (const float*)d_in[4];
    const float* qkv_w     = (const float*)d_in[5];
    const float* qkv_b     = (const float*)d_in[6];
    const float* proj_w    = (const float*)d_in[7];
    const float* proj_b    = (const float*)d_in[8];
    const float* ln1_g     = (const float*)d_in[9];
    const float* ln1_b     = (const float*)d_in[10];
    const float* ln2_g     = (const float*)d_in[11];
    const float* ln2_b     = (const float*)d_in[12];
    const float* mlp_w1    = (const float*)d_in[13];
    const float* mlp_b1    = (const float*)d_in[14];
    const float* mlp_w2    = (const float*)d_in[15];
    const float* mlp_b2    = (const float*)d_in[16];
    const float* norm_g    = (const float*)d_in[17];
    const float* norm_b    = (const float*)d_in[18];
    const float* head_w    = (const float*)d_in[19];
    const float* head_b    = (const float*)d_in[20];

    float *p_pat, *p_emb, *p_x, *p_x2, *p_h, *p_qkv, *p_o, *p_mlp;
    cudaGetSymbolAddress((void**)&p_pat, g_patches);
    cudaGetSymbolAddress((void**)&p_emb, g_embed);
    cudaGetSymbolAddress((void**)&p_x,   g_x);
    cudaGetSymbolAddress((void**)&p_x2,  g_x2);
    cudaGetSymbolAddress((void**)&p_h,   g_h);
    cudaGetSymbolAddress((void**)&p_qkv, g_qkv);
    cudaGetSymbolAddress((void**)&p_o,   g_o);
    cudaGetSymbolAddress((void**)&p_mlp, g_mlp);

    // patch embed (pre-selection: Kahan, 128-tile — bit-identical accumulation)
    {
        int n = BATCH * NPATCH * DIM;
        im2col_k<<<(n + 255) / 256, 256>>>(inputs, p_pat);
        launch_gemm(p_pat, patch_w, patch_b, nullptr, p_emb, BATCH * NPATCH, DIM, DIM, 0, true);
        int n2 = BATCH * LFULL * DIM;
        assemble_k<<<(n2 + 255) / 256, 256>>>(p_emb, cls_token, pos_embed, p_x);
    }

    float* x = p_x;
    int L = LFULL;
    for (int n = 0; n < NLAYER; n++) {
        int M = BATCH * L;
        bool pre = (n <= 3);   // numerics before/at selection stay on exact track
        if (pre) ln_k     <<<M, 256>>>(x, ln1_g + n * DIM, ln1_b + n * DIM, p_h);
        else     ln_fast_k<<<M, 256>>>(x, ln1_g + n * DIM, ln1_b + n * DIM, p_h);
        launch_gemm(p_h, qkv_w + (size_t)n * DIM * 3 * DIM, qkv_b + n * 3 * DIM,
                    nullptr, p_qkv, M, 3 * DIM, DIM, 0, pre);
        if (pre) attn_k     <<<BATCH * NHEAD, 224>>>(p_qkv, p_o, L);
        else     attn_fast_k<<<BATCH * NHEAD, 160>>>(p_qkv, p_o, L);
        launch_gemm(p_o, proj_w + (size_t)n * DIM * DIM, proj_b + n * DIM,
                    x, x, M, DIM, DIM, 2, pre);
        if (pre) ln_k     <<<M, 256>>>(x, ln2_g + n * DIM, ln2_b + n * DIM, p_h);
        else     ln_fast_k<<<M, 256>>>(x, ln2_g + n * DIM, ln2_b + n * DIM, p_h);
        launch_gemm(p_h, mlp_w1 + (size_t)n * DIM * DFF, mlp_b1 + n * DFF,
                    nullptr, p_mlp, M, DFF, DIM, 1, pre);
        launch_gemm(p_mlp, mlp_w2 + (size_t)n * DFF * DIM, mlp_b2 + n * DIM,
                    x, x, M, DIM, DFF, 2, pre);
        if (n == 3) {
            select_k<<<BATCH, 256>>>(x, p_x2);
            x = p_x2;
            L = LKEPT;
        }
    }

    ln_fast_k<<<BATCH * LKEPT, 256>>>(x, norm_g, norm_b, p_h);
    // head: N=100 -> guarded 64x64 kernel path
    launch_gemm(p_h, head_w, head_b, nullptr, (float*)d_out,
                BATCH * LKEPT, NCLS, DIM, 0, false);
}

// round 12
// speedup vs baseline: 1.5658x; 1.0061x over previous
#include <cuda_runtime.h>
#include <math.h>
#include <stdint.h>

// ---------------- constants ----------------
#define BATCH   32
#define CIN     3
#define IMGSZ   224
#define PATCH   16
#define GRIDSZ  14
#define NPATCH  196
#define DIM     768
#define NHEAD   12
#define NLAYER  12
#define DFF     3072
#define DHEAD   64
#define NCLS    100
#define KEEPN   137
#define LFULL   197   // 1 + 196
#define LKEPT   138   // 1 + 137

// ---------------- device scratch (no allocation allowed) ----------------
__device__ float g_patches[BATCH * NPATCH * DIM];
__device__ float g_embed  [BATCH * NPATCH * DIM];
__device__ float g_x      [BATCH * LFULL  * DIM];
__device__ float g_x2     [BATCH * LKEPT  * DIM];
__device__ float g_h      [BATCH * LFULL  * DIM];
__device__ float g_qkv    [BATCH * LFULL  * 3 * DIM];
__device__ float g_o      [BATCH * LFULL  * DIM];
__device__ float g_mlp    [BATCH * LFULL  * DFF];

// ---------------- helpers ----------------
__device__ __forceinline__ float gelu_tanh(float v) {
    float v3 = v * v * v;
    float t  = tanhf(0.7978845608028654f * (v + 0.044715f * v3));
    return 0.5f * v * (1.0f + t);
}

// ---------------- im2col: [B,C,224,224] -> [B*196, 768] ----------------
__global__ void im2col_k(const float* __restrict__ in, float* __restrict__ out) {
    int i = blockIdx.x * blockDim.x + threadIdx.x;
    if (i >= BATCH * NPATCH * DIM) return;
    int d = i % DIM;
    int p = (i / DIM) % NPATCH;
    int b = i / (DIM * NPATCH);
    int c  = d >> 8;
    int py = (d >> 4) & 15;
    int px = d & 15;
    int gy = p / GRIDSZ, gx = p % GRIDSZ;
    out[i] = in[((b * CIN + c) * IMGSZ + gy * PATCH + py) * IMGSZ + gx * PATCH + px];
}

// ---------------- assemble x = [cls|embed] + pos ----------------
__global__ void assemble_k(const float* __restrict__ embed, const float* __restrict__ cls,
                           const float* __restrict__ pos, float* __restrict__ x) {
    int i = blockIdx.x * blockDim.x + threadIdx.x;
    if (i >= BATCH * LFULL * DIM) return;
    int d = i % DIM;
    int r = (i / DIM) % LFULL;
    int b = i / (DIM * LFULL);
    float v = (r == 0) ? cls[d] : embed[((size_t)b * NPATCH + (r - 1)) * DIM + d];
    x[i] = v + pos[r * DIM + d];
}

// ---------------- Kahan GEMM, 64x64 tile, guarded N (head only) ----------------
// flags: bit0 = gelu epilogue, bit1 = residual add
__global__ __launch_bounds__(256) void gemm_kahan_k(
    const float* __restrict__ A, const float* __restrict__ W,
    const float* __restrict__ bias, const float* __restrict__ R,
    float* __restrict__ C, int M, int N, int K, int flags)
{
    __shared__ float As[16][64];
    __shared__ float Ws[16][64];

    int tid = threadIdx.x;
    int tx = tid & 15, ty = tid >> 4;
    int row0 = blockIdx.y << 6;
    int col0 = blockIdx.x << 6;

    int ar = tid >> 2;
    int ak = (tid & 3) << 2;
    int wk = tid >> 4;
    int wn = (tid & 15) << 2;

    bool arow_ok = (row0 + ar) < M;

    float acc[4][4], cmp[4][4];
#pragma unroll
    for (int i = 0; i < 4; i++)
#pragma unroll
        for (int j = 0; j < 4; j++) { acc[i][j] = 0.f; cmp[i][j] = 0.f; }

    for (int k0 = 0; k0 < K; k0 += 16) {
        float4 av = make_float4(0.f, 0.f, 0.f, 0.f);
        if (arow_ok)
            av = *(const float4*)(A + (size_t)(row0 + ar) * K + k0 + ak);
        As[ak + 0][ar] = av.x;
        As[ak + 1][ar] = av.y;
        As[ak + 2][ar] = av.z;
        As[ak + 3][ar] = av.w;

        int wcol = col0 + wn;
        const float* wp = W + (size_t)(k0 + wk) * N + wcol;
        if (wcol + 3 < N) {
            float4 wv = *(const float4*)wp;
            Ws[wk][wn + 0] = wv.x;
            Ws[wk][wn + 1] = wv.y;
            Ws[wk][wn + 2] = wv.z;
            Ws[wk][wn + 3] = wv.w;
        } else {
#pragma unroll
            for (int i = 0; i < 4; i++)
                Ws[wk][wn + i] = (wcol + i < N) ? wp[i] : 0.f;
        }
        __syncthreads();

#pragma unroll
        for (int kk = 0; kk < 16; kk++) {
            float a4[4], w4[4];
            *(float4*)a4 = *(const float4*)&As[kk][ty << 2];
            *(float4*)w4 = *(const float4*)&Ws[kk][tx << 2];
#pragma unroll
            for (int i = 0; i < 4; i++)
#pragma unroll
                for (int j = 0; j < 4; j++) {
                    float y = fmaf(a4[i], w4[j], -cmp[i][j]);
                    float t = acc[i][j] + y;
                    cmp[i][j] = (t - acc[i][j]) - y;
                    acc[i][j] = t;
                }
        }
        __syncthreads();
    }

#pragma unroll
    for (int i = 0; i < 4; i++) {
        int m = row0 + (ty << 2) + i;
        if (m >= M) continue;
#pragma unroll
        for (int j = 0; j < 4; j++) {
            int n = col0 + (tx << 2) + j;
            if (n >= N) continue;
            float v = acc[i][j] + bias[n];
            if (flags & 2) v += R[(size_t)m * N + n];
            if (flags & 1) v = gelu_tanh(v);
            C[(size_t)m * N + n] = v;
        }
    }
}

// ---------------- GEMM, 128x64 tile, 8x4 microtile, double-buffered smem ---------
// Requires N % 64 == 0 and K % 16 == 0. KAHAN=true keeps per-element accumulation
// order over k unchanged (bit-identical to R11) — only memory staging differs.
template <bool KAHAN>
__global__ __launch_bounds__(256) void gemm128_t(
    const float* __restrict__ A, const float* __restrict__ W,
    const float* __restrict__ bias, const float* __restrict__ R,
    float* __restrict__ C, int M, int N, int K, int flags)
{
    __shared__ float As[2][16][128];
    __shared__ float Ws[2][16][64];

    int tid = threadIdx.x;
    int tx = tid & 15, ty = tid >> 4;
    int row0 = blockIdx.y << 7;
    int col0 = blockIdx.x << 6;

    int ar = tid >> 1;            // 0..127
    int ak = (tid & 1) << 3;      // 0 or 8
    int wk = tid >> 4;            // 0..15
    int wn = (tid & 15) << 2;     // 0..60

    bool arow_ok = (row0 + ar) < M;
    const float* arow = A + (size_t)(row0 + ar) * K;
    const float* wrow = W + (size_t)wk * N + col0 + wn;

    float acc[8][4], cmp[8][4];
#pragma unroll
    for (int i = 0; i < 8; i++)
#pragma unroll
        for (int j = 0; j < 4; j++) { acc[i][j] = 0.f; cmp[i][j] = 0.f; }

    // prologue: load tile 0 into buffer 0
    {
#pragma unroll
        for (int u = 0; u < 2; u++) {
            float4 av = make_float4(0.f, 0.f, 0.f, 0.f);
            if (arow_ok) av = *(const float4*)(arow + ak + (u << 2));
            As[0][ak + (u << 2) + 0][ar] = av.x;
            As[0][ak + (u << 2) + 1][ar] = av.y;
            As[0][ak + (u << 2) + 2][ar] = av.z;
            As[0][ak + (u << 2) + 3][ar] = av.w;
        }
        float4 wv = *(const float4*)wrow;
        Ws[0][wk][wn + 0] = wv.x;
        Ws[0][wk][wn + 1] = wv.y;
        Ws[0][wk][wn + 2] = wv.z;
        Ws[0][wk][wn + 3] = wv.w;
    }
    __syncthreads();

    int nTiles = K >> 4;
    for (int t0 = 0; t0 < nTiles; t0++) {
        int buf = t0 & 1;
        int nxt = buf ^ 1;
        bool has_next = (t0 + 1) < nTiles;

        // issue next tile's global loads early (latency overlap with compute)
        float4 avn0 = make_float4(0.f, 0.f, 0.f, 0.f);
        float4 avn1 = make_float4(0.f, 0.f, 0.f, 0.f);
        float4 wvn  = make_float4(0.f, 0.f, 0.f, 0.f);
        if (has_next) {
            int k0n = (t0 + 1) << 4;
            if (arow_ok) {
                avn0 = *(const float4*)(arow + k0n + ak);
                avn1 = *(const float4*)(arow + k0n + ak + 4);
            }
            wvn = *(const float4*)(wrow + (size_t)k0n * N);
        }

        // compute on current buffer
#pragma unroll
        for (int kk = 0; kk < 16; kk++) {
            float a8[8], w4[4];
            *(float4*)&a8[0] = *(const float4*)&As[buf][kk][ty << 3];
            *(float4*)&a8[4] = *(const float4*)&As[buf][kk][(ty << 3) + 4];
            *(float4*)w4 = *(const float4*)&Ws[buf][kk][tx << 2];
#pragma unroll
            for (int i = 0; i < 8; i++)
#pragma unroll
                for (int j = 0; j < 4; j++) {
                    if (KAHAN) {
                        float y = fmaf(a8[i], w4[j], -cmp[i][j]);
                        float t = acc[i][j] + y;
                        cmp[i][j] = (t - acc[i][j]) - y;
                        acc[i][j] = t;
                    } else {
                        acc[i][j] = fmaf(a8[i], w4[j], acc[i][j]);
                    }
                }
        }

        // stage next tile into the other buffer
        if (has_next) {
            As[nxt][ak + 0][ar] = avn0.x;
            As[nxt][ak + 1][ar] = avn0.y;
            As[nxt][ak + 2][ar] = avn0.z;
            As[nxt][ak + 3][ar] = avn0.w;
            As[nxt][ak + 4][ar] = avn1.x;
            As[nxt][ak + 5][ar] = avn1.y;
            As[nxt][ak + 6][ar] = avn1.z;
            As[nxt][ak + 7][ar] = avn1.w;
            Ws[nxt][wk][wn + 0] = wvn.x;
            Ws[nxt][wk][wn + 1] = wvn.y;
            Ws[nxt][wk][wn + 2] = wvn.z;
            Ws[nxt][wk][wn + 3] = wvn.w;
        }
        __syncthreads();
    }

#pragma unroll
    for (int i = 0; i < 8; i++) {
        int m = row0 + (ty << 3) + i;
        if (m >= M) continue;
        int n0 = col0 + (tx << 2);
#pragma unroll
        for (int j = 0; j < 4; j++) {
            int n = n0 + j;
            float v = acc[i][j] + bias[n];
            if (flags & 2) v += R[(size_t)m * N + n];
            if (flags & 1) v = gelu_tanh(v);
            C[(size_t)m * N + n] = v;
        }
    }
}

// ---------------- LayerNorm, fp64 reductions (pre-selection path) ----------------
__global__ __launch_bounds__(256) void ln_k(const float* __restrict__ x,
                                            const float* __restrict__ gg,
                                            const float* __restrict__ bb,
                                            float* __restrict__ out) {
    int row = blockIdx.x;
    int t = threadIdx.x;
    const float* xr = x + (size_t)row * DIM;
    float v0 = xr[t], v1 = xr[t + 256], v2 = xr[t + 512];

    __shared__ double red[8];
    double s = (double)v0 + (double)v1 + (double)v2;
#pragma unroll
    for (int o = 16; o > 0; o >>= 1) s += __shfl_xor_sync(0xffffffffu, s, o);
    if ((t & 31) == 0) red[t >> 5] = s;
    __syncthreads();
    double tot = 0.0;
#pragma unroll
    for (int w = 0; w < 8; w++) tot += red[w];
    float mean = (float)(tot * (1.0 / 768.0));
    __syncthreads();

    float d0 = v0 - mean, d1 = v1 - mean, d2 = v2 - mean;
    double sq = (double)d0 * d0 + (double)d1 * d1 + (double)d2 * d2;
#pragma unroll
    for (int o = 16; o > 0; o >>= 1) sq += __shfl_xor_sync(0xffffffffu, sq, o);
    if ((t & 31) == 0) red[t >> 5] = sq;
    __syncthreads();
    double vtot = 0.0;
#pragma unroll
    for (int w = 0; w < 8; w++) vtot += red[w];
    float var = (float)(vtot * (1.0 / 768.0));
    float rstd = rsqrtf(var + 1e-6f);

    float* orow = out + (size_t)row * DIM;
    orow[t]       = d0 * rstd * gg[t]       + bb[t];
    orow[t + 256] = d1 * rstd * gg[t + 256] + bb[t + 256];
    orow[t + 512] = d2 * rstd * gg[t + 512] + bb[t + 512];
}

// ---------------- LayerNorm, fp32 reductions (post-selection fast path) ----------
__global__ __launch_bounds__(256) void ln_fast_k(const float* __restrict__ x,
                                                 const float* __restrict__ gg,
                                                 const float* __restrict__ bb,
                                                 float* __restrict__ out) {
    int row = blockIdx.x;
    int t = threadIdx.x;
    const float* xr = x + (size_t)row * DIM;
    float v0 = xr[t], v1 = xr[t + 256], v2 = xr[t + 512];

    __shared__ float red[8];
    float s = v0 + v1 + v2;
#pragma unroll
    for (int o = 16; o > 0; o >>= 1) s += __shfl_xor_sync(0xffffffffu, s, o);
    if ((t & 31) == 0) red[t >> 5] = s;
    __syncthreads();
    float tot = 0.f;
#pragma unroll
    for (int w = 0; w < 8; w++) tot += red[w];
    float mean = tot * (1.0f / 768.0f);
    __syncthreads();

    float d0 = v0 - mean, d1 = v1 - mean, d2 = v2 - mean;
    float sq = d0 * d0 + d1 * d1 + d2 * d2;
#pragma unroll
    for (int o = 16; o > 0; o >>= 1) sq += __shfl_xor_sync(0xffffffffu, sq, o);
    if ((t & 31) == 0) red[t >> 5] = sq;
    __syncthreads();
    float vtot = 0.f;
#pragma unroll
    for (int w = 0; w < 8; w++) vtot += red[w];
    float var = vtot * (1.0f / 768.0f);
    float rstd = rsqrtf(var + 1e-6f);

    float* orow = out + (size_t)row * DIM;
    orow[t]       = d0 * rstd * gg[t]       + bb[t];
    orow[t + 256] = d1 * rstd * gg[t + 256] + bb[t + 256];
    orow[t + 512] = d2 * rstd * gg[t + 512] + bb[t + 512];
}

// ---------------- attention, two-pass exact max (pre-selection path) -------------
__global__ __launch_bounds__(224) void attn_k(const float* __restrict__ qkv,
                                              float* __restrict__ o, int L) {
    int b = blockIdx.x / NHEAD;
    int h = blockIdx.x % NHEAD;
    __shared__ float Ks[64][DHEAD];
    __shared__ float Vs[64][DHEAD];
    int t = threadIdx.x;

    const float* base = qkv + (size_t)b * L * (3 * DIM);

    float qv[DHEAD];
    if (t < L) {
        const float* qp = base + (size_t)t * (3 * DIM) + h * DHEAD;
#pragma unroll
        for (int d = 0; d < DHEAD; d++) qv[d] = qp[d];
    }

    float mmax = -3.0e38f;
    for (int j0 = 0; j0 < L; j0 += 64) {
        int jn = min(64, L - j0);
        for (int e = t; e < jn * 16; e += blockDim.x) {
            int jj = e >> 4, q = e & 15;
            const float* kp = base + (size_t)(j0 + jj) * (3 * DIM) + DIM + h * DHEAD;
            *(float4*)&Ks[jj][q << 2] = *(const float4*)(kp + (q << 2));
        }
        __syncthreads();
        if (t < L) {
            for (int jj = 0; jj < jn; jj++) {
                float s = 0.f;
#pragma unroll
                for (int d = 0; d < DHEAD; d++) s = fmaf(qv[d], Ks[jj][d], s);
                mmax = fmaxf(mmax, s * 0.125f);
            }
        }
        __syncthreads();
    }

    float acc[DHEAD];
    float lsum = 0.f, lcmp = 0.f;
    if (t < L) {
#pragma unroll
        for (int d = 0; d < DHEAD; d++) acc[d] = 0.f;
    }
    for (int j0 = 0; j0 < L; j0 += 64) {
        int jn = min(64, L - j0);
        for (int e = t; e < jn * 32; e += blockDim.x) {
            int jj = e >> 5, q = e & 31;
            const float* kp = base + (size_t)(j0 + jj) * (3 * DIM) + DIM + h * DHEAD;
            if (q < 16)
                *(float4*)&Ks[jj][q << 2] = *(const float4*)(kp + (q << 2));
            else
                *(float4*)&Vs[jj][(q - 16) << 2] = *(const float4*)(kp + DIM + ((q - 16) << 2));
        }
        __syncthreads();
        if (t < L) {
            for (int jj = 0; jj < jn; jj++) {
                float s = 0.f;
#pragma unroll
                for (int d = 0; d < DHEAD; d++) s = fmaf(qv[d], Ks[jj][d], s);
                float p = expf(s * 0.125f - mmax);
                float y = p - lcmp;
                float ts = lsum + y;
                lcmp = (ts - lsum) - y;
                lsum = ts;
#pragma unroll
                for (int d = 0; d < DHEAD; d++) acc[d] = fmaf(p, Vs[jj][d], acc[d]);
            }
        }
        __syncthreads();
    }

    if (t < L) {
        float inv = 1.0f / lsum;
        float* op = o + ((size_t)(b * L + t)) * DIM + h * DHEAD;
#pragma unroll
        for (int d = 0; d < DHEAD; d++) op[d] = acc[d] * inv;
    }
}

// ---------------- attention, single-pass online softmax (post-selection) ---------
__global__ __launch_bounds__(160) void attn_fast_k(const float* __restrict__ qkv,
                                                   float* __restrict__ o, int L) {
    int b = blockIdx.x / NHEAD;
    int h = blockIdx.x % NHEAD;
    __shared__ float Ks[64][DHEAD];
    __shared__ float Vs[64][DHEAD];
    int t = threadIdx.x;

    const float* base = qkv + (size_t)b * L * (3 * DIM);

    float qv[DHEAD], acc[DHEAD];
    float mmax = -3.0e38f, lsum = 0.f;
    if (t < L) {
        const float* qp = base + (size_t)t * (3 * DIM) + h * DHEAD;
#pragma unroll
        for (int d = 0; d < DHEAD; d++) { qv[d] = qp[d]; acc[d] = 0.f; }
    }

    for (int j0 = 0; j0 < L; j0 += 64) {
        int jn = min(64, L - j0);
        for (int e = t; e < jn * 32; e += blockDim.x) {
            int jj = e >> 5, q = e & 31;
            const float* kp = base + (size_t)(j0 + jj) * (3 * DIM) + DIM + h * DHEAD;
            if (q < 16)
                *(float4*)&Ks[jj][q << 2] = *(const float4*)(kp + (q << 2));
            else
                *(float4*)&Vs[jj][(q - 16) << 2] = *(const float4*)(kp + DIM + ((q - 16) << 2));
        }
        __syncthreads();
        if (t < L) {
            for (int jj = 0; jj < jn; jj++) {
                float s = 0.f;
#pragma unroll
                for (int d = 0; d < DHEAD; d++) s = fmaf(qv[d], Ks[jj][d], s);
                s *= 0.125f;
                float nm   = fmaxf(mmax, s);
                float corr = __expf(mmax - nm);
                float p    = __expf(s - nm);
                lsum = lsum * corr + p;
#pragma unroll
                for (int d = 0; d < DHEAD; d++) acc[d] = fmaf(acc[d], corr, p * Vs[jj][d]);
                mmax = nm;
            }
        }
        __syncthreads();
    }

    if (t < L) {
        float inv = 1.0f / lsum;
        float* op = o + ((size_t)(b * L + t)) * DIM + h * DHEAD;
#pragma unroll
        for (int d = 0; d < DHEAD; d++) op[d] = acc[d] * inv;
    }
}

// ---------------- token selection after layer 3 (fp64 sims) ----------------
__global__ __launch_bounds__(256) void select_k(const float* __restrict__ x,
                                                float* __restrict__ x2) {
    int b = blockIdx.x;
    int t = threadIdx.x;
    __shared__ float cls_s[DIM];
    __shared__ float sim[NPATCH];
    __shared__ int   order[KEEPN];

    for (int d = t; d < DIM; d += 256) cls_s[d] = x[(size_t)(b * LFULL) * DIM + d];
    __syncthreads();

    if (t < NPATCH) {
        const float* row = x + (size_t)(b * LFULL + 1 + t) * DIM;
        double dot = 0.0, n2 = 0.0, c2 = 0.0;
        for (int d = 0; d < DIM; d++) {
            double xv = (double)row[d], cv = (double)cls_s[d];
            dot += cv * xv; n2 += xv * xv; c2 += cv * cv;
        }
        double den = sqrt(c2) * sqrt(n2);
        sim[t] = (float)(dot / fmax(den, 1e-8));
    }
    __syncthreads();

    if (t < NPATCH) {
        float sv = sim[t];
        int r = 0;
        for (int q = 0; q < NPATCH; q++) {
            float o = sim[q];
            r += (o > sv) || (o == sv && q < t);
        }
        if (r < KEEPN) order[r] = t;
    }
    __syncthreads();

    for (int e = t; e < LKEPT * DIM; e += 256) {
        int r = e / DIM, d = e % DIM;
        int src = (r == 0) ? 0 : 1 + order[r - 1];
        x2[(size_t)(b * LKEPT + r) * DIM + d] = x[(size_t)(b * LFULL + src) * DIM + d];
    }
}

// ---------------- host driver ----------------
static void launch_gemm(const float* A, const float* W, const float* bias,
                        const float* R, float* C, int M, int N, int K, int flags,
                        bool kahan) {
    if (N & 63) {
        dim3 grid((N + 63) / 64, (M + 63) / 64);
        gemm_kahan_k<<<grid, 256>>>(A, W, bias, R, C, M, N, K, flags);
    } else {
        dim3 grid(N / 64, (M + 127) / 128);
        if (kahan)
            gemm128_t<true><<<grid, 256>>>(A, W, bias, R, C, M, N, K, flags);
        else
            gemm128_t<false><<<grid, 256>>>(A, W, bias, R, C, M, N, K, flags);
    }
}

extern "C" void kernel_launch(void* const* d_in, const int* in_sizes, int n_in,
                              void* d_out, int out_size) {
    const float* inputs    = (const float*)d_in[0];
    const float* patch_w   = (const float*)d_in[1];
    const float* patch_b   = (const float*)d_in[2];
    const float* cls_token = (const float*)d_in[3];
    const float* pos_embed = (const float*)d_in[4];
    const float* qkv_w     = (const float*)d_in[5];
    const float* qkv_b     = (const float*)d_in[6];
    const float* proj_w    = (const float*)d_in[7];
    const float* proj_b    = (const float*)d_in[8];
    const float* ln1_g     = (const float*)d_in[9];
    const float* ln1_b     = (const float*)d_in[10];
    const float* ln2_g     = (const float*)d_in[11];
    const float* ln2_b     = (const float*)d_in[12];
    const float* mlp_w1    = (const float*)d_in[13];
    const float* mlp_b1    = (const float*)d_in[14];
    const float* mlp_w2    = (const float*)d_in[15];
    const float* mlp_b2    = (const float*)d_in[16];
    const float* norm_g    = (const float*)d_in[17];
    const float* norm_b    = (const float*)d_in[18];
    const float* head_w    = (const float*)d_in[19];
    const float* head_b    = (const float*)d_in[20];

    float *p_pat, *p_emb, *p_x, *p_x2, *p_h, *p_qkv, *p_o, *p_mlp;
    cudaGetSymbolAddress((void**)&p_pat, g_patches);
    cudaGetSymbolAddress((void**)&p_emb, g_embed);
    cudaGetSymbolAddress((void**)&p_x,   g_x);
    cudaGetSymbolAddress((void**)&p_x2,  g_x2);
    cudaGetSymbolAddress((void**)&p_h,   g_h);
    cudaGetSymbolAddress((void**)&p_qkv, g_qkv);
    cudaGetSymbolAddress((void**)&p_o,   g_o);
    cudaGetSymbolAddress((void**)&p_mlp, g_mlp);

    // patch embed (pre-selection: Kahan, double-buffered 128-tile — bit-identical)
    {
        int n = BATCH * NPATCH * DIM;
        im2col_k<<<(n + 255) / 256, 256>>>(inputs, p_pat);
        launch_gemm(p_pat, patch_w, patch_b, nullptr, p_emb, BATCH * NPATCH, DIM, DIM, 0, true);
        int n2 = BATCH * LFULL * DIM;
        assemble_k<<<(n2 + 255) / 256, 256>>>(p_emb, cls_token, pos_embed, p_x);
    }

    float* x = p_x;
    int L = LFULL;
    for (int n = 0; n < NLAYER; n++) {
        int M = BATCH * L;
        bool pre = (n <= 3);   // numerics before/at selection stay on exact track
        if (pre) ln_k     <<<M, 256>>>(x, ln1_g + n * DIM, ln1_b + n * DIM, p_h);
        else     ln_fast_k<<<M, 256>>>(x, ln1_g + n * DIM, ln1_b + n * DIM, p_h);
        launch_gemm(p_h, qkv_w + (size_t)n * DIM * 3 * DIM, qkv_b + n * 3 * DIM,
                    nullptr, p_qkv, M, 3 * DIM, DIM, 0, pre);
        if (pre) attn_k     <<<BATCH * NHEAD, 224>>>(p_qkv, p_o, L);
        else     attn_fast_k<<<BATCH * NHEAD, 160>>>(p_qkv, p_o, L);
        launch_gemm(p_o, proj_w + (size_t)n * DIM * DIM, proj_b + n * DIM,
                    x, x, M, DIM, DIM, 2, pre);
        if (pre) ln_k     <<<M, 256>>>(x, ln2_g + n * DIM, ln2_b + n * DIM, p_h);
        else     ln_fast_k<<<M, 256>>>(x, ln2_g + n * DIM, ln2_b + n * DIM, p_h);
        launch_gemm(p_h, mlp_w1 + (size_t)n * DIM * DFF, mlp_b1 + n * DFF,
                    nullptr, p_mlp, M, DFF, DIM, 1, pre);
        launch_gemm(p_mlp, mlp_w2 + (size_t)n * DFF * DIM, mlp_b2 + n * DIM,
                    x, x, M, DIM, DFF, 2, pre);
        if (n == 3) {
            select_k<<<BATCH, 256>>>(x, p_x2);
            x = p_x2;
            L = LKEPT;
        }
    }

    ln_fast_k<<<BATCH * LKEPT, 256>>>(x, norm_g, norm_b, p_h);
    // head: N=100 -> guarded 64x64 kernel path
    launch_gemm(p_h, head_w, head_b, nullptr, (float*)d_out,
                BATCH * LKEPT, NCLS, DIM, 0, false);
}